// round 7
// baseline (speedup 1.0000x reference)
#include <cuda_runtime.h>

#define B_ROWS 16384
#define HID 256
#define COMP 32
#define T_TOK 8
#define NVOC 257
#define VSTRIDE 261          // padded row stride for sorted vocab
#define NF 0.0625f
#define EPS_THR 1e-6f
#define NGROUP 2048
#define ROWS_PB 16

typedef unsigned long long u64;

// ---- packed fp32x2 helpers (sm_103a FFMA2 path; ptxas never auto-fuses) ----
__device__ __forceinline__ u64 pk(float lo, float hi) {
    u64 r; asm("mov.b64 %0,{%1,%2};" : "=l"(r) : "f"(lo), "f"(hi)); return r;
}
__device__ __forceinline__ void ffma2(u64& d, u64 a, u64 b) {
    asm("fma.rn.f32x2 %0,%1,%2,%0;" : "+l"(d) : "l"(a), "l"(b));
}
__device__ __forceinline__ float upk_sum(u64 v) {
    float lo, hi; asm("mov.b64 {%0,%1},%2;" : "=f"(lo), "=f"(hi) : "l"(v));
    return lo + hi;
}
// one LDS.128 -> two packed f32x2 operands, no pack MOVs
__device__ __forceinline__ void lds2(u64& a, u64& b, unsigned addr) {
    asm("ld.shared.v2.u64 {%0,%1},[%2];" : "=l"(a), "=l"(b) : "r"(addr));
}

// ---------------- device scratch (no allocations allowed) ----------------
__device__ float g_msg[B_ROWS * HID];
__device__ float g_vocs[COMP * VSTRIDE];           // per-dim sorted vocab
__device__ u64 g_Wq64[(HID / 2) * HID];            // pk(WQ[2k][t],WQ[2k+1][t])
__device__ u64 g_Wk64[(HID / 2) * HID];            // pk(WK[2k][t],WK[2k+1][t])
__device__ u64 g_Wmv64[(HID / 2) * 64];            // k-pairs of [Wmu|Wvar] cols

// ---------------- Kernel 0a: per-dim bitonic sort of vocab columns --------
__global__ __launch_bounds__(512) void sort_kernel(const float* __restrict__ vocab)
{
    __shared__ float buf[512];
    const int d = blockIdx.x;
    const int t = threadIdx.x;
    buf[t] = (t < NVOC) ? vocab[t * COMP + d] : 1e30f;
    __syncthreads();
    for (int k = 2; k <= 512; k <<= 1) {
        for (int j = k >> 1; j > 0; j >>= 1) {
            int ixj = t ^ j;
            if (ixj > t) {
                float a = buf[t], b = buf[ixj];
                bool up = ((t & k) == 0);
                if ((a > b) == up) { buf[t] = b; buf[ixj] = a; }
            }
            __syncthreads();
        }
    }
    if (t < NVOC) g_vocs[d * VSTRIDE + t] = buf[t];
}

// ---------------- Kernel 0b: pre-pack weights into f32x2 u64 tables -------
__global__ __launch_bounds__(256) void pack_kernel(
    const float* __restrict__ WQ, const float* __restrict__ WK,
    const float* __restrict__ Wmu, const float* __restrict__ Wvar)
{
    const int k2 = blockIdx.x;      // 0..127
    const int t  = threadIdx.x;     // 0..255
    g_Wq64[k2 * HID + t] = pk(WQ[(2 * k2) * HID + t], WQ[(2 * k2 + 1) * HID + t]);
    g_Wk64[k2 * HID + t] = pk(WK[(2 * k2) * HID + t], WK[(2 * k2 + 1) * HID + t]);
    if (t < 64) {
        float a0, a1;
        if (t < 32) { a0 = Wmu[(2 * k2) * COMP + t];        a1 = Wmu[(2 * k2 + 1) * COMP + t]; }
        else        { a0 = Wvar[(2 * k2) * COMP + t - 32];  a1 = Wvar[(2 * k2 + 1) * COMP + t - 32]; }
        g_Wmv64[k2 * 64 + t] = pk(a0, a1);
    }
}

// branchless lower-bound nearest-neighbor squared distance on the sorted
// per-dim vocab column (bitwise identical to the full 257-entry min scan).
// arr points into g_vocs (global; L1-resident, ~33 KB hot working set).
__device__ __forceinline__ float nearest_sq(const float* arr, float x)
{
    int p = 0;
    #pragma unroll
    for (int s = 256; s; s >>= 1) {
        int q = p + s;
        if (q <= NVOC) { if (__ldg(arr + q - 1) <= x) p = q; }
    }
    float lo = (p > 0)    ? __ldg(arr + p - 1) : 1e30f;
    float hi = (p < NVOC) ? __ldg(arr + p)     : 1e30f;
    float a = x - lo, b = x - hi;
    return fminf(a * a, b * b);
}

// ---------------- Kernel 1: persistent fused main kernel -------------------
// 16 rows/block, 256 threads, 2 blocks/SM (128-reg budget, no spills).
// smem (floats):
//   ha_s   [16*256]      0      (hs tile; e*V per iter; GEMM staging)
//   msg_s  [16*256]      4096
//   Wmv_s  u64[128*64]   8192   (16384 floats; [Wmu|Wvar] k-pair packed)
//   tok_s  [16*32]       24576
//   eos_s  [32]          25088
//   maskf  [16]          25120
//   fin_s  [16]          25136
//   part_s [16*8]        25152
// total 25280 floats = 101120 B, x2 = 202 KB/SM (L1 residue ~26 KB for vocab).
__global__ void __launch_bounds__(256, 2) main_kernel(
    const float* __restrict__ hs,
    const float* __restrict__ bQ, const float* __restrict__ bK,
    const float* __restrict__ bmu, const float* __restrict__ bvar,
    const float* __restrict__ vocab, const float* __restrict__ eps)
{
    extern __shared__ float sm[];
    float* ha_s   = sm;
    float* msg_s  = sm + 4096;
    float* Wmv_s  = sm + 8192;          // viewed as u64[8192]
    float* tok_s  = sm + 24576;
    float* eos_s  = sm + 25088;
    float* maskf  = sm + 25120;
    float* fin_s  = sm + 25136;
    float* part_s = sm + 25152;

    const int t = threadIdx.x;
    const int r0 = blockIdx.x * ROWS_PB;
    const int w = t >> 5, l = t & 31;
    const unsigned ha_sa  = (unsigned)__cvta_generic_to_shared(ha_s);
    const unsigned tok_sa = (unsigned)__cvta_generic_to_shared(tok_s);
    const u64* Wmv_p = (const u64*)Wmv_s;

    // ---- block-resident setup ----
    {   // Wmv_s: 64 KB bulk copy from prepacked global table
        const float4* src = (const float4*)g_Wmv64;
        float4* dst = (float4*)Wmv_s;
        #pragma unroll
        for (int i = 0; i < 16; i++) dst[t + i * 256] = src[t + i * 256];
    }
    if (t < COMP) eos_s[t] = vocab[256 * COMP + t];
    if (t < ROWS_PB) { maskf[t] = 1.0f; fin_s[t] = 0.0f; }
    {
        const float4* src = (const float4*)(hs + (size_t)r0 * HID);
        float4* dst = (float4*)ha_s;
        #pragma unroll
        for (int i = 0; i < 4; i++) dst[t + i * 256] = src[t + i * 256];
    }
    __syncthreads();

    // ---- Q = (hs@WQ+bQ)*NF ; V = hs@WK+bK  (prepacked-u64 FFMA2 GEMM) ----
    float Qr[16], Vr[16], kacc[16];
    {
        const float bq = bQ[t], bk = bK[t];
        u64 aq[16], av[16];
        #pragma unroll
        for (int m = 0; m < 16; m++) { aq[m] = pk(bq, 0.0f); av[m] = pk(bk, 0.0f); }
        #pragma unroll 2
        for (int k = 0; k < HID; k += 4) {
            const int k2 = k >> 1;
            u64 wq01 = g_Wq64[(size_t)k2 * HID + t];
            u64 wq23 = g_Wq64[(size_t)(k2 + 1) * HID + t];
            u64 wv01 = g_Wk64[(size_t)k2 * HID + t];
            u64 wv23 = g_Wk64[(size_t)(k2 + 1) * HID + t];
            #pragma unroll
            for (int m = 0; m < 16; m++) {
                u64 a01, a23;
                lds2(a01, a23, ha_sa + (unsigned)((m * HID + k) * 4));
                ffma2(aq[m], a01, wq01); ffma2(aq[m], a23, wq23);
                ffma2(av[m], a01, wv01); ffma2(av[m], a23, wv23);
            }
        }
        #pragma unroll
        for (int m = 0; m < 16; m++) {
            Qr[m] = upk_sum(aq[m]) * NF;
            Vr[m] = upk_sum(av[m]);
            kacc[m] = bk;
        }
    }

    // ---- token recurrence ----
    #pragma unroll 1
    for (int it = 0; it < T_TOK; it++) {
        __syncthreads();   // A: orders prev phase4 writes (tok/msg/mask/fin)

        // Phase 1: incremental K update with previous token (32 new msg cols)
        if (it > 0) {
            const u64* wkp = g_Wk64 + (size_t)((it - 1) * 16) * HID + t;
            u64 acc2[16];
            #pragma unroll
            for (int m = 0; m < 16; m++) acc2[m] = 0ull;
            #pragma unroll
            for (int c = 0; c < COMP; c += 4) {
                const int c2 = c >> 1;
                u64 w01 = wkp[(size_t)c2 * HID];
                u64 w23 = wkp[(size_t)(c2 + 1) * HID];
                #pragma unroll
                for (int m = 0; m < 16; m++) {
                    u64 a01, a23;
                    lds2(a01, a23, tok_sa + (unsigned)((m * COMP + c) * 4));
                    ffma2(acc2[m], a01, w01); ffma2(acc2[m], a23, w23);
                }
            }
            #pragma unroll
            for (int m = 0; m < 16; m++) kacc[m] += upk_sum(acc2[m]);
        }

        // Phase 2: e = exp(-(Q*K)); write e*V to ha_s; per-row partial sums
        #pragma unroll
        for (int m = 0; m < 16; m++) {
            float e = __expf(-(Qr[m] * (kacc[m] * NF)));
            ha_s[m * HID + t] = e * Vr[m];
            float s = e;
            #pragma unroll
            for (int o = 16; o; o >>= 1) s += __shfl_xor_sync(0xffffffffu, s, o);
            if (l == 0) part_s[m * 8 + w] = s;
        }
        __syncthreads();   // B: ha_s + part_s visible

        // Phase 3a: raw (e*V) @ [Wmu|Wvar]; weights from SMEM (staged once),
        // thread owns 1 output col for all 16 rows over a 64-wide k-partition
        {
            const int c  = t & 63;
            const int kp = t >> 6;
            const int k0 = kp * 64;
            u64 acc2[16];
            #pragma unroll
            for (int m = 0; m < 16; m++) acc2[m] = 0ull;
            #pragma unroll 2
            for (int k = k0; k < k0 + 64; k += 4) {
                const int k2 = k >> 1;
                u64 w01 = Wmv_p[k2 * 64 + c];
                u64 w23 = Wmv_p[(k2 + 1) * 64 + c];
                #pragma unroll
                for (int m = 0; m < 16; m++) {
                    u64 a01, a23;
                    lds2(a01, a23, ha_sa + (unsigned)((m * HID + k) * 4));
                    ffma2(acc2[m], a01, w01); ffma2(acc2[m], a23, w23);
                }
            }
            __syncthreads();   // D: all ha_s reads done -> reuse as staging
            #pragma unroll
            for (int m = 0; m < 16; m++)
                ha_s[kp * 1024 + m * 64 + c] = upk_sum(acc2[m]);
        }
        __syncthreads();   // E: staging visible

        // Phase 3b: kp-reduce + inv + bias, sample, nearest-vocab (L1), mask
        {
            const int m  = t >> 4;
            const int c0 = (t & 15) * 2;
            float smu0 = 0.0f, smu1 = 0.0f, slv0 = 0.0f, slv1 = 0.0f;
            #pragma unroll
            for (int kp = 0; kp < 4; kp++) {
                float2 a = *(const float2*)&ha_s[kp * 1024 + m * 64 + c0];
                float2 b = *(const float2*)&ha_s[kp * 1024 + m * 64 + 32 + c0];
                smu0 += a.x; smu1 += a.y;
                slv0 += b.x; slv1 += b.y;
            }
            float rs = 0.0f;
            #pragma unroll
            for (int ww = 0; ww < 8; ww++) rs += part_s[m * 8 + ww];
            const float iv = 1.0f / rs;
            float2 bm = *(const float2*)&bmu[c0];
            float2 bv = *(const float2*)&bvar[c0];
            float amu0 = smu0 * iv + bm.x, amu1 = smu1 * iv + bm.y;
            float alv0 = slv0 * iv + bv.x, alv1 = slv1 * iv + bv.y;
            const size_t r = (size_t)(r0 + m);
            float2 e2 = *(const float2*)&eps[((size_t)it * B_ROWS + r) * COMP + c0];
            float x0 = e2.x * __expf(0.5f * alv0) + amu0;
            float x1 = e2.y * __expf(0.5f * alv1) + amu1;
            float d0 = nearest_sq(g_vocs + c0 * VSTRIDE, x0);
            float d1 = nearest_sq(g_vocs + (c0 + 1) * VSTRIDE, x1);
            const float mk = maskf[m];
            tok_s[m * COMP + c0]     = d0 * mk;
            tok_s[m * COMP + c0 + 1] = d1 * mk;
        }
        __syncthreads();   // G: tok_s visible

        // Phase 4: EOS / repeat-hit logic; warp w owns rows 2w, 2w+1
        {
            #pragma unroll
            for (int mm = 0; mm < 2; mm++) {
                const int m = w * 2 + mm;
                float tk = tok_s[m * COMP + l];
                float ev = eos_s[l];
                float de = tk - ev;
                float se = de * de;
                #pragma unroll
                for (int o = 16; o; o >>= 1) se += __shfl_xor_sync(0xffffffffu, se, o);
                bool hit = (se < EPS_THR);
                for (int p = 0; p < it; p++) {
                    float dp = tk - msg_s[m * HID + p * COMP + l];
                    float sp = dp * dp;
                    #pragma unroll
                    for (int o = 16; o; o >>= 1) sp += __shfl_xor_sync(0xffffffffu, sp, o);
                    hit = hit || (sp < EPS_THR);
                }
                float fin = fin_s[m];
                bool new_eos = hit && (fin == 0.0f);
                float outv = new_eos ? ev : tk;
                msg_s[m * HID + it * COMP + l] = outv;
                tok_s[m * COMP + l] = outv;
                if (l == 0 && hit) { maskf[m] = 0.0f; fin_s[m] = 1.0f; }
            }
        }
    }

    // ---- flush message to global for the tail ----
    __syncthreads();
    {
        float4* dst = (float4*)(g_msg + (size_t)r0 * HID);
        const float4* src = (const float4*)msg_s;
        #pragma unroll
        for (int i = 0; i < 4; i++) dst[t + i * 256] = src[t + i * 256];
    }
}

// ---------------- Kernel 2: fused tail: group-sum/7 @Wsum -> @Whead+relu ---
__global__ __launch_bounds__(256) void tail_kernel(
    const float* __restrict__ Wsum, const float* __restrict__ bsum,
    const float* __restrict__ Whead, const float* __restrict__ bhead,
    float* __restrict__ out)
{
    __shared__ __align__(16) float A_s[16 * HID];
    const int t = threadIdx.x;
    const int g0 = blockIdx.x * 16;
    const unsigned A_sa = (unsigned)__cvta_generic_to_shared(A_s);

    #pragma unroll
    for (int m = 0; m < 16; m++) {
        float s = 0.0f;
        #pragma unroll
        for (int a = 0; a < 8; a++)
            s += g_msg[(size_t)((g0 + m) * 8 + a) * HID + t];
        A_s[m * HID + t] = s * (1.0f / 7.0f);
    }
    __syncthreads();

    float res[16];
    {
        u64 acc2[16];
        const float bb = bsum[t];
        #pragma unroll
        for (int m = 0; m < 16; m++) acc2[m] = pk(bb, 0.0f);
        #pragma unroll 2
        for (int k = 0; k < HID; k += 4) {
            float w0 = Wsum[(k+0)*HID+t], w1 = Wsum[(k+1)*HID+t];
            float w2 = Wsum[(k+2)*HID+t], w3 = Wsum[(k+3)*HID+t];
            u64 w01 = pk(w0, w1), w23 = pk(w2, w3);
            #pragma unroll
            for (int m = 0; m < 16; m++) {
                u64 a01, a23;
                lds2(a01, a23, A_sa + (unsigned)((m * HID + k) * 4));
                ffma2(acc2[m], a01, w01); ffma2(acc2[m], a23, w23);
            }
        }
        #pragma unroll
        for (int m = 0; m < 16; m++) res[m] = upk_sum(acc2[m]);
    }
    __syncthreads();
    #pragma unroll
    for (int m = 0; m < 16; m++) A_s[m * HID + t] = res[m];
    __syncthreads();

    {
        u64 acc2[16];
        const float bb = bhead[t];
        #pragma unroll
        for (int m = 0; m < 16; m++) acc2[m] = pk(bb, 0.0f);
        #pragma unroll 2
        for (int k = 0; k < HID; k += 4) {
            float w0 = Whead[(k+0)*HID+t], w1 = Whead[(k+1)*HID+t];
            float w2 = Whead[(k+2)*HID+t], w3 = Whead[(k+3)*HID+t];
            u64 w01 = pk(w0, w1), w23 = pk(w2, w3);
            #pragma unroll
            for (int m = 0; m < 16; m++) {
                u64 a01, a23;
                lds2(a01, a23, A_sa + (unsigned)((m * HID + k) * 4));
                ffma2(acc2[m], a01, w01); ffma2(acc2[m], a23, w23);
            }
        }
        #pragma unroll
        for (int m = 0; m < 16; m++) res[m] = upk_sum(acc2[m]);
    }
    #pragma unroll
    for (int m = 0; m < 16; m++) {
        float v = fmaxf(res[m], 0.0f);
        #pragma unroll
        for (int a = 0; a < 8; a++)
            out[(size_t)((g0 + m) * 8 + a) * HID + t] = v;
    }
}

// ---------------- launch ---------------------------------------------------
extern "C" void kernel_launch(void* const* d_in, const int* in_sizes, int n_in,
                              void* d_out, int out_size)
{
    const float* hs    = (const float*)d_in[0];
    const float* eps   = (const float*)d_in[1];
    const float* WQ    = (const float*)d_in[2];
    const float* bQ    = (const float*)d_in[3];
    const float* WK    = (const float*)d_in[4];
    const float* bK    = (const float*)d_in[5];
    const float* Wmu   = (const float*)d_in[6];
    const float* bmu   = (const float*)d_in[7];
    const float* Wvar  = (const float*)d_in[8];
    const float* bvar  = (const float*)d_in[9];
    const float* vocab = (const float*)d_in[10];
    const float* Wsum  = (const float*)d_in[11];
    const float* bsum  = (const float*)d_in[12];
    const float* Whead = (const float*)d_in[13];
    const float* bhead = (const float*)d_in[14];
    float* out = (float*)d_out;

    const int smem_main = 25280 * (int)sizeof(float);   // 101120 B
    cudaFuncSetAttribute(main_kernel,
                         cudaFuncAttributeMaxDynamicSharedMemorySize, smem_main);

    sort_kernel<<<COMP, 512>>>(vocab);
    pack_kernel<<<HID / 2, 256>>>(WQ, WK, Wmu, Wvar);
    main_kernel<<<B_ROWS / ROWS_PB, 256, smem_main>>>(
        hs, bQ, bK, bmu, bvar, vocab, eps);
    tail_kernel<<<NGROUP / 16, 256>>>(Wsum, bsum, Whead, bhead, out);
}